// round 16
// baseline (speedup 1.0000x reference)
#include <cuda_runtime.h>
#include <cuda_fp16.h>
#include <math.h>
#include <stdint.h>

// Problem shape: n=2, l=2048, d_model=1024, h=16, e=64
#define NB 2
#define SEQL 2048
#define DM 1024
#define NH 16
#define DE 64
#define ROWS (NB * SEQL)          // 4096

// ---------------- scratch ----------------
__device__ float  g_cwp[8 * NB * DM];         // cond partials
__device__ __half g_xnh[ROWS * DM];
__device__ __half g_qh[NB*NH*SEQL*DE];
__device__ __half g_kh[NB*NH*SEQL*DE];
__device__ __half g_vh[NB*NH*SEQL*DE];
__device__ __half g_oh[ROWS * DM];
__device__ __half g_wqh[DM * 3 * DM], g_wql[DM * 3 * DM];
__device__ __half g_woh[DM * DM];

// ---------------- helpers ----------------
static __device__ __forceinline__ uint32_t smem_u32(const void* p) {
    uint32_t a;
    asm("{ .reg .u64 t; cvta.to.shared.u64 t, %1; cvt.u32.u64 %0, t; }" : "=r"(a) : "l"(p));
    return a;
}
static __device__ __forceinline__ void cpasync16(uint32_t dst, const void* src) {
    asm volatile("cp.async.cg.shared.global [%0], [%1], 16;" :: "r"(dst), "l"(src));
}
#define CP_COMMIT() asm volatile("cp.async.commit_group;" ::: "memory")
#define CP_WAIT1()  asm volatile("cp.async.wait_group 1;"  ::: "memory")
static __device__ __forceinline__ void ldsm4(uint32_t* r, uint32_t a) {
    asm volatile("ldmatrix.sync.aligned.m8n8.x4.shared.b16 {%0,%1,%2,%3}, [%4];"
        : "=r"(r[0]), "=r"(r[1]), "=r"(r[2]), "=r"(r[3]) : "r"(a));
}
static __device__ __forceinline__ void ldsm4t(uint32_t* r, uint32_t a) {
    asm volatile("ldmatrix.sync.aligned.m8n8.x4.trans.shared.b16 {%0,%1,%2,%3}, [%4];"
        : "=r"(r[0]), "=r"(r[1]), "=r"(r[2]), "=r"(r[3]) : "r"(a));
}
static __device__ __forceinline__ void mma_f16(float* c, const uint32_t* a, const uint32_t* b) {
    asm volatile("mma.sync.aligned.m16n8k16.row.col.f32.f16.f16.f32 "
        "{%0,%1,%2,%3}, {%4,%5,%6,%7}, {%8,%9}, {%0,%1,%2,%3};"
        : "+f"(c[0]), "+f"(c[1]), "+f"(c[2]), "+f"(c[3])
        : "r"(a[0]), "r"(a[1]), "r"(a[2]), "r"(a[3]), "r"(b[0]), "r"(b[1]));
}
static __device__ __forceinline__ float fast_exp2(float x) {
    float y; asm("ex2.approx.f32 %0, %1;" : "=f"(y) : "f"(x)); return y;
}
static __device__ __forceinline__ uint32_t pack2f(float a, float b) {
    __half2 h = __floats2half2_rn(a, b);
    return *(uint32_t*)&h;
}

// ---------------- cond GEMM: K-split partials ----------------
__global__ void cond_partial_kernel(const float* __restrict__ cond,
                                    const float* __restrict__ w_cond)
{
    __shared__ float cs[128];
    const int n  = blockIdx.y;
    const int ks = blockIdx.z;
    if (threadIdx.x < 128)
        cs[threadIdx.x] = cond[n * DM + ks * 128 + threadIdx.x];
    __syncthreads();
    const int j = blockIdx.x * blockDim.x + threadIdx.x;
    float acc = 0.f;
#pragma unroll 8
    for (int k = 0; k < 128; k++)
        acc = fmaf(cs[k], w_cond[(size_t)(ks * 128 + k) * DM + j], acc);
    g_cwp[(ks * NB + n) * DM + j] = acc;
}

// ---------------- fused: rmsnorm(x) [inline cond reduce] + splits ----------------
#define FP_RMS   ROWS
#define FP_WQ    (DM * 3 * DM / 256)     // 12288
#define FP_WO    (DM * DM / 256)         // 4096
__global__ void fused_pre_kernel(const float* __restrict__ x,
                                 const float* __restrict__ w_qkv,
                                 const float* __restrict__ w_out)
{
    const int b = blockIdx.x;
    const int t = threadIdx.x;
    if (b < FP_RMS) {
        const int row = b;
        const int n = row / SEQL;
        float4 v = *(const float4*)(x + (size_t)row * DM + t * 4);
        float ss = v.x * v.x + v.y * v.y + v.z * v.z + v.w * v.w;
#pragma unroll
        for (int o = 16; o > 0; o >>= 1)
            ss += __shfl_xor_sync(0xffffffffu, ss, o);
        __shared__ float ws[8];
        if ((t & 31) == 0) ws[t >> 5] = ss;
        __syncthreads();
        float tot = ws[0]+ws[1]+ws[2]+ws[3]+ws[4]+ws[5]+ws[6]+ws[7];
        float rinv = rsqrtf(tot * (1.0f / DM) + 1e-6f);
        // cond reduce inline (same order as before: 1 + sum over ks)
        float4 cwv = make_float4(1.f, 1.f, 1.f, 1.f);
#pragma unroll
        for (int ks = 0; ks < 8; ks++) {
            float4 p = *(const float4*)(g_cwp + (ks * NB + n) * DM + t * 4);
            cwv.x += p.x; cwv.y += p.y; cwv.z += p.z; cwv.w += p.w;
        }
        size_t base = (size_t)row * DM + t * 4;
        *(uint32_t*)(g_xnh + base)     = pack2f(v.x * cwv.x * rinv, v.y * cwv.y * rinv);
        *(uint32_t*)(g_xnh + base + 2) = pack2f(v.z * cwv.z * rinv, v.w * cwv.w * rinv);
    } else if (b < FP_RMS + FP_WQ) {
        int i = (b - FP_RMS) * 256 + t;
        float v = w_qkv[i];
        __half hh = __float2half_rn(v);
        g_wqh[i] = hh;
        // lo only needed for Q/K columns (<2048); V region is single-term
        int col = i - (i / (3 * DM)) * (3 * DM);
        if (col < 2 * DM)
            g_wql[i] = __float2half_rn(v - __half2float(hh));
    } else {
        int i = (b - FP_RMS - FP_WQ) * 256 + t;
        g_woh[i] = __float2half_rn(w_out[i]);
    }
}

// ---------------- GEMM core: BM=128, BN=128, BK=32, 3-stage, 1- or 2-term ----------------
#define GM_ASTRIDE 80
#define GM_BSTRIDE 272
#define GM_A_SZ (128 * GM_ASTRIDE)            // 10240
#define GM_B_SZ (32 * GM_BSTRIDE)             // 8704
#define GM_BUF (GM_A_SZ + 2*GM_B_SZ)          // 27648
#define GEMM_SMEM (3 * GM_BUF)                // 82944

static __device__ __forceinline__ void gemm_load(uint32_t smb, int bufi,
    const __half* Ah, const __half* Bh, const __half* Bl,
    int m0, int n0, int k0, int K, int N, int tid, int terms)
{
    uint32_t base = smb + bufi * GM_BUF;
    const int ar = tid >> 1, ac = (tid & 1) * 16;
    const __half* pah = Ah + (size_t)(m0 + ar) * K + k0 + ac;
    cpasync16(base + ar*GM_ASTRIDE + ac*2,      pah);
    cpasync16(base + ar*GM_ASTRIDE + ac*2 + 16, pah + 8);
    const int br = tid >> 3, bc = (tid & 7) * 16;
    const __half* pbh = Bh + (size_t)(k0 + br) * N + n0 + bc;
    uint32_t bb = base + GM_A_SZ;
    cpasync16(bb + br*GM_BSTRIDE + bc*2,      pbh);
    cpasync16(bb + br*GM_BSTRIDE + bc*2 + 16, pbh + 8);
    if (terms == 2) {
        const __half* pbl = Bl + (size_t)(k0 + br) * N + n0 + bc;
        cpasync16(bb + GM_B_SZ + br*GM_BSTRIDE + bc*2,      pbl);
        cpasync16(bb + GM_B_SZ + br*GM_BSTRIDE + bc*2 + 16, pbl + 8);
    }
}

#define GEMM_MAINLOOP(Ah, Bh, Bl, K, N, TERMS)                                  \
    const int nk = (K) / 32;                                                    \
    gemm_load(smb, 0, Ah, Bh, Bl, m0, n0, 0, K, N, tid, TERMS);                 \
    CP_COMMIT();                                                                \
    gemm_load(smb, 1, Ah, Bh, Bl, m0, n0, 32, K, N, tid, TERMS);                \
    CP_COMMIT();                                                                \
    for (int s = 0; s < nk; s++) {                                              \
        CP_WAIT1();                                                             \
        __syncthreads();                                                        \
        if (s + 2 < nk)                                                         \
            gemm_load(smb, (s + 2) % 3, Ah, Bh, Bl, m0, n0, (s + 2) * 32, K, N, tid, TERMS); \
        CP_COMMIT();                                                            \
        uint32_t base = smb + (s % 3) * GM_BUF;                                 \
        uint32_t a_h = base;                                                    \
        uint32_t b_h = base + GM_A_SZ, b_l = b_h + GM_B_SZ;                     \
        _Pragma("unroll")                                                       \
        for (int kt = 0; kt < 2; kt++) {                                        \
            uint32_t bfh[4][4], bfl[4][4];                                      \
            const uint32_t brow = kt * 16 + (lane & 7) + ((lane & 8) ? 8 : 0);  \
            const uint32_t bcol = wn * 2 + ((lane & 16) ? 16 : 0);              \
            _Pragma("unroll")                                                   \
            for (int np = 0; np < 4; np++) {                                    \
                ldsm4t(bfh[np], b_h + brow * GM_BSTRIDE + bcol + np * 32);      \
                if (TERMS == 2)                                                 \
                    ldsm4t(bfl[np], b_l + brow * GM_BSTRIDE + bcol + np * 32);  \
            }                                                                   \
            _Pragma("unroll")                                                   \
            for (int m = 0; m < 2; m++) {                                       \
                uint32_t afh[4];                                                \
                const uint32_t arow = wm + m * 16 + (lane & 15);                \
                const uint32_t acol = kt * 32 + ((lane & 16) ? 16 : 0);         \
                ldsm4(afh, a_h + arow * GM_ASTRIDE + acol);                     \
                _Pragma("unroll")                                               \
                for (int np = 0; np < 4; np++) {                                \
                    mma_f16(acc[m][2*np],   afh, bfh[np]);                      \
                    mma_f16(acc[m][2*np+1], afh, bfh[np] + 2);                  \
                    if (TERMS == 2) {                                           \
                        mma_f16(acc[m][2*np],   afh, bfl[np]);                  \
                        mma_f16(acc[m][2*np+1], afh, bfl[np] + 2);              \
                    }                                                           \
                }                                                               \
            }                                                                   \
        }                                                                       \
    }

// ---------------- QKV GEMM with fused qk-rmsnorm + rope epilogue ----------------
// 1D grid, heavy-first tile order: ids [0,512) = Q/K tiles (2-term),
// ids [512,768) = V tiles (1-term).
__global__ __launch_bounds__(256, 2) void qkv_gemm_kernel(
    const __half* __restrict__ Ah,
    const __half* __restrict__ Bh, const __half* __restrict__ Bl,
    const float* __restrict__ pos, const float* __restrict__ qk_scale)
{
    extern __shared__ char sm[];
    const uint32_t smb = smem_u32(sm);
    const int tid = threadIdx.x, lane = tid & 31, wid = tid >> 5;

    int tx, ty;
    {
        const int id = blockIdx.x;
        if (id < 512) { tx = id & 15;  ty = id >> 4; }
        else { const int v = id - 512; tx = 16 + (v & 7); ty = v >> 3; }
    }
    const int m0 = ty * 128, n0 = tx * 128;
    const int wm = (wid & 3) * 32, wn = (wid >> 2) * 64;
    const int K = DM, N = 3 * DM;
    const int region = n0 >> 10;                    // 0 Q, 1 K, 2 V

    float acc[2][8][4];
#pragma unroll
    for (int m = 0; m < 2; m++)
#pragma unroll
        for (int n = 0; n < 8; n++)
#pragma unroll
            for (int r = 0; r < 4; r++) acc[m][n][r] = 0.f;

    if (region != 2) {
        GEMM_MAINLOOP(Ah, Bh, Bl, K, N, 2)
    } else {
        GEMM_MAINLOOP(Ah, Bh, Bl, K, N, 1)
    }

    const int g = lane >> 2, tg = lane & 3;
    const int head = ((n0 + wn) & 1023) >> 6;
    const size_t hb = (size_t)head * SEQL * DE;

    if (region == 2) {
#pragma unroll
        for (int m = 0; m < 2; m++)
#pragma unroll
            for (int rr = 0; rr < 2; rr++) {
                const int row = m0 + wm + m*16 + g + rr*8;
                const int nb = row >> 11, l = row & (SEQL - 1);
                const size_t ob = (size_t)nb * NH * SEQL * DE + hb + (size_t)l * DE;
#pragma unroll
                for (int n = 0; n < 8; n++) {
                    const int c = n*8 + tg*2;
                    *(uint32_t*)(g_vh + ob + c) = pack2f(acc[m][n][rr*2], acc[m][n][rr*2+1]);
                }
            }
    } else {
        __half* dst = region ? g_kh : g_qh;
        float sc = expf(0.5f * fminf(qk_scale[head], 4.6051701860f) - 1.0397207708f);
        if (region == 0) sc *= 0.18033688011112042f;   // log2(e)/8 folded into Q
        float fr0[4], fr1[4];
#pragma unroll
        for (int n = 0; n < 4; n++) {
            const int c0 = n*8 + tg*2;
            fr0[n] = expf(1.14472988584940017f + (float)((c0 & 15) * 16 + head) * (2.30258509299404568f / 256.0f));
            fr1[n] = expf(1.14472988584940017f + (float)(((c0+1) & 15) * 16 + head) * (2.30258509299404568f / 256.0f));
        }
#pragma unroll
        for (int m = 0; m < 2; m++)
#pragma unroll
            for (int rr = 0; rr < 2; rr++) {
                float ss = 0.f;
#pragma unroll
                for (int n = 0; n < 8; n++) {
                    float a0 = acc[m][n][rr*2], a1 = acc[m][n][rr*2+1];
                    ss += a0*a0 + a1*a1;
                }
                ss += __shfl_xor_sync(0xffffffffu, ss, 1);
                ss += __shfl_xor_sync(0xffffffffu, ss, 2);
                const float rinv = sc * rsqrtf(ss * (1.0f / DE) + 1e-6f);

                const int row = m0 + wm + m*16 + g + rr*8;
                const int nb = row >> 11, l = row & (SEQL - 1);
                const size_t ob = (size_t)nb * NH * SEQL * DE + hb + (size_t)l * DE;
#pragma unroll
                for (int n = 0; n < 4; n++) {
                    const int c0 = n*8 + tg*2;
                    const float pv = pos[(size_t)row * 2 + (c0 >> 4)];
                    float s0, cth0, s1, cth1;
                    __sincosf(pv * fr0[n], &s0, &cth0);
                    __sincosf(pv * fr1[n], &s1, &cth1);
                    const float x1a = acc[m][n][rr*2]     * rinv;
                    const float x1b = acc[m][n][rr*2+1]   * rinv;
                    const float x2a = acc[m][n+4][rr*2]   * rinv;
                    const float x2b = acc[m][n+4][rr*2+1] * rinv;
                    *(uint32_t*)(dst + ob + c0)      = pack2f(x1a*cth0 - x2a*s0, x1b*cth1 - x2b*s1);
                    *(uint32_t*)(dst + ob + c0 + 32) = pack2f(x2a*cth0 + x1a*s0, x2b*cth1 + x1b*s1);
                }
            }
    }
}

// ---------------- out GEMM (single-term, fp32 output) ----------------
__global__ __launch_bounds__(256, 2) void out_gemm_kernel(
    const __half* __restrict__ Ah, const __half* __restrict__ Bh,
    float* __restrict__ C)
{
    extern __shared__ char sm[];
    const uint32_t smb = smem_u32(sm);
    const int tid = threadIdx.x, lane = tid & 31, wid = tid >> 5;
    const int m0 = blockIdx.y * 128, n0 = blockIdx.x * 128;
    const int wm = (wid & 3) * 32, wn = (wid >> 2) * 64;
    const int K = DM, N = DM;

    float acc[2][8][4];
#pragma unroll
    for (int m = 0; m < 2; m++)
#pragma unroll
        for (int n = 0; n < 8; n++)
#pragma unroll
            for (int r = 0; r < 4; r++) acc[m][n][r] = 0.f;

    GEMM_MAINLOOP(Ah, Bh, Bh, K, N, 1)

    const int g = lane >> 2, tg = lane & 3;
#pragma unroll
    for (int m = 0; m < 2; m++)
#pragma unroll
        for (int rr = 0; rr < 2; rr++) {
            int row = m0 + wm + m * 16 + g + rr * 8;
#pragma unroll
            for (int n = 0; n < 8; n++) {
                int col = n0 + wn + n * 8 + tg * 2;
                *(float2*)(C + (size_t)row * N + col) =
                    make_float2(acc[m][n][rr*2], acc[m][n][rr*2+1]);
            }
        }
}

// ---------------- attention: 256 threads, 8 warps (16 q-rows each), 3-stage ----------------
#define AT_STRIDE 144
#define AT_QH 0
#define AT_KV0 (128 * AT_STRIDE)              // 18432
#define AT_ARR (64 * AT_STRIDE)               // 9216 per array
#define AT_BUF (2 * AT_ARR)                   // 18432 (Kh, Vh)
#define NKT (SEQL / 64)                       // 32
#define ATTN_SMEM (AT_KV0 + 3 * AT_BUF)       // 73728

static __device__ __forceinline__ void attn_load_kv(uint32_t smb, size_t bh,
                                                    int tid, int t, int bufi)
{
    const int k0 = t * 64;
    const int r  = tid >> 2;
    const int hc = (tid & 3) * 16;
    uint32_t base = smb + AT_KV0 + bufi * AT_BUF + r * AT_STRIDE + hc * 2;
    const __half* s0 = g_kh + (bh + k0 + r) * DE + hc;
    const __half* s1 = g_vh + (bh + k0 + r) * DE + hc;
#pragma unroll
    for (int c = 0; c < 2; c++) {
        cpasync16(base + 0*AT_ARR + c*16, s0 + c*8);
        cpasync16(base + 1*AT_ARR + c*16, s1 + c*8);
    }
}

__global__ __launch_bounds__(256, 2) void attn_mma_kernel()
{
    extern __shared__ char sm[];
    const uint32_t smb = smem_u32(sm);
    const int tid = threadIdx.x, lane = tid & 31, wid = tid >> 5;
    const int q0 = blockIdx.x * 128, head = blockIdx.y, b = blockIdx.z;
    const size_t bh = (size_t)(b * NH + head) * SEQL;

    {
        const int r = tid >> 1, hc = (tid & 1) * 32;
        const __half* qh = g_qh + (bh + q0 + r) * DE + hc;
        uint32_t dh = smb + AT_QH + r * AT_STRIDE + hc * 2;
#pragma unroll
        for (int c = 0; c < 4; c++)
            cpasync16(dh + c*16, qh + c*8);
    }
    attn_load_kv(smb, bh, tid, 0, 0);
    CP_COMMIT();
    attn_load_kv(smb, bh, tid, 1, 1);
    CP_COMMIT();
    CP_WAIT1();
    __syncthreads();

    uint32_t qfr[4][4];
#pragma unroll
    for (int kt = 0; kt < 4; kt++) {
        const uint32_t qrow = wid*16 + (lane & 15);
        const uint32_t qcol = kt * 32 + ((lane & 16) ? 16 : 0);
        ldsm4(qfr[kt], smb + AT_QH + qrow * AT_STRIDE + qcol);
    }

    float O[8][4];
#pragma unroll
    for (int n = 0; n < 8; n++)
#pragma unroll
        for (int r = 0; r < 4; r++) O[n][r] = 0.f;
    float lsacc[4] = {0.f, 0.f, 0.f, 0.f};
    const uint32_t ones2[2] = {0x3C003C00u, 0x3C003C00u};

    for (int t = 0; t < NKT; t++) {
        CP_WAIT1();
        __syncthreads();
        if (t + 2 < NKT)
            attn_load_kv(smb, bh, tid, t + 2, (t + 2) % 3);
        CP_COMMIT();

        uint32_t kb  = smb + AT_KV0 + (t % 3) * AT_BUF;
        uint32_t kh_b = kb, vh_b = kb + AT_ARR;

        float S[8][4];
#pragma unroll
        for (int n = 0; n < 8; n++)
#pragma unroll
            for (int r = 0; r < 4; r++) S[n][r] = 0.f;

#pragma unroll
        for (int kt = 0; kt < 4; kt++) {
            uint32_t kfh[4][4];
            const uint32_t krow = (lane & 7) + ((lane & 16) ? 8 : 0);
            const uint32_t kcol = kt * 32 + ((lane & 8) ? 16 : 0);
#pragma unroll
            for (int np = 0; np < 4; np++)
                ldsm4(kfh[np], kh_b + (np*16 + krow) * AT_STRIDE + kcol);
#pragma unroll
            for (int np = 0; np < 4; np++) {
                mma_f16(S[2*np],   qfr[kt], kfh[np]);
                mma_f16(S[2*np+1], qfr[kt], kfh[np] + 2);
            }
        }

        uint32_t pa[4][4];
#pragma unroll
        for (int n = 0; n < 8; n++) {
            float p0 = fast_exp2(S[n][0]);
            float p1 = fast_exp2(S[n][1]);
            float p2 = fast_exp2(S[n][2]);
            float p3 = fast_exp2(S[n][3]);
            const int kt = n >> 1, rb = (n & 1) * 2;
            pa[kt][rb]     = pack2f(p0, p1);
            pa[kt][rb + 1] = pack2f(p2, p3);
        }

#pragma unroll
        for (int kt = 0; kt < 4; kt++)
            mma_f16(lsacc, pa[kt], ones2);

#pragma unroll
        for (int kt = 0; kt < 4; kt++) {
            uint32_t vfh[4][4];
            const uint32_t vrow = kt*16 + (lane & 7) + ((lane & 8) ? 8 : 0);
            const uint32_t vcol = ((lane & 16) ? 16 : 0);
#pragma unroll
            for (int np = 0; np < 4; np++)
                ldsm4t(vfh[np], vh_b + vrow * AT_STRIDE + np*32 + vcol);
#pragma unroll
            for (int np = 0; np < 4; np++) {
                mma_f16(O[2*np],   pa[kt], vfh[np]);
                mma_f16(O[2*np+1], pa[kt], vfh[np] + 2);
            }
        }
    }

    const int g = lane >> 2, tg = lane & 3;
#pragma unroll
    for (int rr = 0; rr < 2; rr++) {
        const int row = q0 + wid*16 + g + rr*8;
        const float inv = 1.0f / lsacc[rr*2];
        const size_t rb = ((size_t)b * SEQL + row) * DM + head * DE;
#pragma unroll
        for (int n = 0; n < 8; n++) {
            const int col = n*8 + tg*2;
            *(uint32_t*)(g_oh + rb + col) =
                pack2f(O[n][rr*2] * inv, O[n][rr*2+1] * inv);
        }
    }
}

// ---------------- launch ----------------
extern "C" void kernel_launch(void* const* d_in, const int* in_sizes, int n_in,
                              void* d_out, int out_size)
{
    const float* x        = (const float*)d_in[0];
    const float* pos      = (const float*)d_in[1];
    const float* cond     = (const float*)d_in[2];
    const float* w_cond   = (const float*)d_in[3];
    const float* w_qkv    = (const float*)d_in[4];
    const float* qk_scale = (const float*)d_in[5];
    const float* w_out    = (const float*)d_in[6];
    float* out = (float*)d_out;

    __half *p_xnh, *p_oh, *p_wqh, *p_wql, *p_woh;
    cudaGetSymbolAddress((void**)&p_xnh, g_xnh);
    cudaGetSymbolAddress((void**)&p_oh,  g_oh);
    cudaGetSymbolAddress((void**)&p_wqh, g_wqh);
    cudaGetSymbolAddress((void**)&p_wql, g_wql);
    cudaGetSymbolAddress((void**)&p_woh, g_woh);

    static int s_attr = 0;
    if (!s_attr) {
        cudaFuncSetAttribute(attn_mma_kernel,
                             cudaFuncAttributeMaxDynamicSharedMemorySize, ATTN_SMEM);
        cudaFuncSetAttribute(qkv_gemm_kernel,
                             cudaFuncAttributeMaxDynamicSharedMemorySize, GEMM_SMEM);
        cudaFuncSetAttribute(out_gemm_kernel,
                             cudaFuncAttributeMaxDynamicSharedMemorySize, GEMM_SMEM);
        s_attr = 1;
    }

    cond_partial_kernel<<<dim3(DM/256, NB, 8), 256>>>(cond, w_cond);         // 0
    fused_pre_kernel<<<FP_RMS + FP_WQ + FP_WO, 256>>>(x, w_qkv, w_out);      // 1
    qkv_gemm_kernel<<<768, 256, GEMM_SMEM>>>(                                // 2
        p_xnh, p_wqh, p_wql, pos, qk_scale);
    attn_mma_kernel<<<dim3(SEQL/128, NH, NB), 256, ATTN_SMEM>>>();           // 3 (profiled)
    out_gemm_kernel<<<dim3(DM/128, ROWS/128), 256, GEMM_SMEM>>>(             // 4
        p_oh, p_woh, out);
}